// round 2
// baseline (speedup 1.0000x reference)
#include <cuda_runtime.h>
#include <math.h>

// Problem shape (fixed for this dataset): B=32, A=3, S=80, NC=80
#define NCLS   80
#define CH     85          // 5 + NC
#define TCH    6
#define S2     6400        // S*S
#define NA     3
#define EPSF   1e-7f
#define MAXBLK 4096

// per-block partials: [nool_sum, noobj_cnt, box_sum, objl_sum, cls_sum, obj_cnt]
__device__ double g_part[MAXBLK * 6];

__device__ __forceinline__ float warp_sum(float v) {
    #pragma unroll
    for (int o = 16; o; o >>= 1) v += __shfl_xor_sync(0xffffffffu, v, o);
    return v;
}
__device__ __forceinline__ float warp_max(float v) {
    #pragma unroll
    for (int o = 16; o; o >>= 1) v = fmaxf(v, __shfl_xor_sync(0xffffffffu, v, o));
    return v;
}

__global__ __launch_bounds__(256)
void yolo_loss_main(const float* __restrict__ pred,
                    const float* __restrict__ tgt,
                    const float* __restrict__ anc,
                    int cells)
{
    const int warp_global = (blockIdx.x * blockDim.x + threadIdx.x) >> 5;
    const int lane = threadIdx.x & 31;
    const int c0 = warp_global * 32;

    float a_nool = 0.f, a_ncnt = 0.f, a_box = 0.f, a_objl = 0.f, a_cls = 0.f, a_ocnt = 0.f;

    if (c0 < cells) {
        const int c = c0 + lane;
        const bool valid = (c < cells);
        float t0 = valid ? __ldg(&tgt[(long long)c * TCH]) : -1.0f;
        float p0 = valid ? __ldg(&pred[(long long)c * CH]) : 0.0f;

        // ---- no-object BCE-with-logits on channel 0 (t == 0 cells) ----
        if (valid && t0 == 0.0f) {
            // bce(z, 0) = max(z,0) + log1p(exp(-|z|))
            a_nool += fmaxf(p0, 0.f) + log1pf(expf(-fabsf(p0)));
            a_ncnt += 1.f;
        }

        // ---- cooperative processing of obj cells (t == 1) ----
        unsigned bal = __ballot_sync(0xffffffffu, valid && (t0 == 1.0f));
        if (lane == 0) a_ocnt += (float)__popc(bal);

        while (bal) {
            const int i = __ffs(bal) - 1;
            bal &= bal - 1;
            const int cc = c0 + i;
            const long long base = (long long)cc * CH;
            const float p0i = __shfl_sync(0xffffffffu, p0, i);

            // class logits: lane l holds k = l, l+32, l+64  (channels 5..84)
            float v0 = __ldg(&pred[base + 5  + lane]);
            float v1 = __ldg(&pred[base + 37 + lane]);
            float v2 = (lane < 16) ? __ldg(&pred[base + 69 + lane]) : 0.0f;
            const bool has2 = (lane < 16);

            // log-softmax pieces
            float mx = fmaxf(fmaxf(v0, v1), has2 ? v2 : -INFINITY);
            mx = warp_max(mx);
            float e  = expf(v0 - mx) + expf(v1 - mx) + (has2 ? expf(v2 - mx) : 0.f);
            float sx = v0 + v1 + (has2 ? v2 : 0.f);
            e  = warp_sum(e);
            sx = warp_sum(sx);
            const float lse = mx + logf(e);

            // box pred channels 1..4 and target channels 1..5
            float pb = (lane < 4) ? __ldg(&pred[base + 1 + lane]) : 0.f;
            const float p1 = __shfl_sync(0xffffffffu, pb, 0);
            const float p2 = __shfl_sync(0xffffffffu, pb, 1);
            const float p3 = __shfl_sync(0xffffffffu, pb, 2);
            const float p4 = __shfl_sync(0xffffffffu, pb, 3);
            float tb = (lane < 5) ? __ldg(&tgt[(long long)cc * TCH + 1 + lane]) : 0.f;
            const float t1 = __shfl_sync(0xffffffffu, tb, 0);
            const float t2 = __shfl_sync(0xffffffffu, tb, 1);
            const float t3 = __shfl_sync(0xffffffffu, tb, 2);
            const float t4 = __shfl_sync(0xffffffffu, tb, 3);
            const float t5 = __shfl_sync(0xffffffffu, tb, 4);

            // gather class logit for target class k
            const int k = (int)t5;
            const int srcl = k & 31;
            const float s0 = __shfl_sync(0xffffffffu, v0, srcl);
            const float s1 = __shfl_sync(0xffffffffu, v1, srcl);
            const float s2 = __shfl_sync(0xffffffffu, v2, srcl);
            const float xk = (k < 32) ? s0 : ((k < 64) ? s1 : s2);

            const float logpy   = xk - lse;
            const float sumlogp = sx - (float)NCLS * lse;
            const float ce = -(0.9f * logpy + (0.1f / (float)NCLS) * sumlogp);

            // object loss: BCE-with-logits applied to sigmoid(p0) with t=1 (reference quirk)
            const float sg = 1.f / (1.f + expf(-p0i));
            const float ol = fmaxf(sg, 0.f) - sg + log1pf(expf(-fabsf(sg)));

            // decoded box + CIoU
            const int aidx = (cc / S2) % NA;
            const float aw = __ldg(&anc[aidx * 2 + 0]);
            const float ah = __ldg(&anc[aidx * 2 + 1]);
            const float bx = 1.f / (1.f + expf(-p1));
            const float by = 1.f / (1.f + expf(-p2));
            const float bw = expf(p3) * aw;
            const float bh = expf(p4) * ah;

            const float x1a = bx - bw * 0.5f, x1b = bx + bw * 0.5f;
            const float y1a = by - bh * 0.5f, y1b = by + bh * 0.5f;
            const float x2a = t1 - t3 * 0.5f, x2b = t1 + t3 * 0.5f;
            const float y2a = t2 - t4 * 0.5f, y2b = t2 + t4 * 0.5f;
            const float iw = fmaxf(fminf(x1b, x2b) - fmaxf(x1a, x2a), 0.f);
            const float ih = fmaxf(fminf(y1b, y2b) - fmaxf(y1a, y2a), 0.f);
            const float inter = iw * ih;
            const float uni = bw * bh + t3 * t4 - inter + EPSF;
            const float iou = inter / uni;
            const float cw = fmaxf(x1b, x2b) - fminf(x1a, x2a);
            const float chh = fmaxf(y1b, y2b) - fminf(y1a, y2a);
            const float c2 = cw * cw + chh * chh + EPSF;
            const float rho2 = (t1 - bx) * (t1 - bx) + (t2 - by) * (t2 - by);
            const float fo = 4.0f / ((float)M_PI * (float)M_PI);
            const float dv = atanf(t3 / (t4 + EPSF)) - atanf(bw / (bh + EPSF));
            const float v = fo * dv * dv;
            const float alpha = v / (1.f - iou + v + EPSF);
            const float ciou = iou - rho2 / c2 - alpha * v;

            if (lane == 0) {
                a_box  += (1.f - ciou);
                a_objl += ol;
                a_cls  += ce;
            }
        }
    }

    // warp reduce the 6 accumulators (a_box/a_objl/a_cls/a_ocnt live on lane0 only)
    a_nool = warp_sum(a_nool);
    a_ncnt = warp_sum(a_ncnt);
    a_box  = warp_sum(a_box);
    a_objl = warp_sum(a_objl);
    a_cls  = warp_sum(a_cls);
    a_ocnt = warp_sum(a_ocnt);

    __shared__ float sh[8][6];
    const int wid = threadIdx.x >> 5;
    if (lane == 0) {
        sh[wid][0] = a_nool; sh[wid][1] = a_ncnt; sh[wid][2] = a_box;
        sh[wid][3] = a_objl; sh[wid][4] = a_cls;  sh[wid][5] = a_ocnt;
    }
    __syncthreads();
    if (threadIdx.x == 0) {
        const int nw = blockDim.x >> 5;
        #pragma unroll
        for (int q = 0; q < 6; q++) {
            double d = 0.0;
            for (int w = 0; w < nw; w++) d += (double)sh[w][q];
            g_part[(long long)blockIdx.x * 6 + q] = d;
        }
    }
}

__global__ __launch_bounds__(256)
void yolo_loss_final(float* __restrict__ out, int nblk)
{
    __shared__ double sh[256][6];
    double acc[6] = {0, 0, 0, 0, 0, 0};
    for (int i = threadIdx.x; i < nblk; i += 256) {
        #pragma unroll
        for (int q = 0; q < 6; q++) acc[q] += g_part[(long long)i * 6 + q];
    }
    #pragma unroll
    for (int q = 0; q < 6; q++) sh[threadIdx.x][q] = acc[q];
    __syncthreads();
    for (int s = 128; s; s >>= 1) {
        if (threadIdx.x < s) {
            #pragma unroll
            for (int q = 0; q < 6; q++) sh[threadIdx.x][q] += sh[threadIdx.x + s][q];
        }
        __syncthreads();
    }
    if (threadIdx.x == 0) {
        const double nool = sh[0][0] / fmax(sh[0][1], 1.0);
        const double od   = fmax(sh[0][5], 1.0);
        const double box  = sh[0][2] / od;
        const double objl = sh[0][3] / od;
        const double cls  = sh[0][4] / od;
        out[0] = (float)(2.0 * box + objl + nool + cls);
    }
}

extern "C" void kernel_launch(void* const* d_in, const int* in_sizes, int n_in,
                              void* d_out, int out_size)
{
    (void)n_in; (void)out_size;
    const float* pred = (const float*)d_in[0];
    const float* tgt  = (const float*)d_in[1];
    const float* anc  = (const float*)d_in[2];
    float* out = (float*)d_out;

    const int cells = in_sizes[0] / CH;               // 614400
    int blocks = (cells + 255) / 256;                 // warp handles 32 cells, 8 warps/block
    if (blocks > MAXBLK) blocks = MAXBLK;             // (not hit at this shape)

    yolo_loss_main<<<blocks, 256>>>(pred, tgt, anc, cells);
    yolo_loss_final<<<1, 256>>>(out, blocks);
}

// round 4
// speedup vs baseline: 1.1720x; 1.1720x over previous
#include <cuda_runtime.h>
#include <math.h>

// Problem shape (fixed for this dataset): B=32, A=3, S=80, NC=80
#define NCLS   80
#define CH     85          // 5 + NC
#define TCH    6
#define S2     6400        // S*S
#define NA     3
#define EPSF   1e-7f
#define BLOCKS 592         // 4 * 148 SMs
#define TPB    256
#define NWARPS (BLOCKS * (TPB / 32))

// per-block partials: [nool_sum, noobj_cnt, box_sum, objl_sum, cls_sum, obj_cnt]
__device__ double   g_part[BLOCKS * 6];
__device__ unsigned g_done = 0;

__device__ __forceinline__ float warp_sum(float v) {
    #pragma unroll
    for (int o = 16; o; o >>= 1) v += __shfl_xor_sync(0xffffffffu, v, o);
    return v;
}
__device__ __forceinline__ float warp_max(float v) {
    #pragma unroll
    for (int o = 16; o; o >>= 1) v = fmaxf(v, __shfl_xor_sync(0xffffffffu, v, o));
    return v;
}
__device__ __forceinline__ double warp_sum_d(double v) {
    #pragma unroll
    for (int o = 16; o; o >>= 1) v += __shfl_xor_sync(0xffffffffu, v, o);
    return v;
}

// Process one 32-cell chunk starting at c0. T0..T5 hold the warp's coalesced
// 192-float target block (lane l owns flat elements l, l+32, ..., l+160);
// p0 is this lane's pred objectness logit for cell c0+lane.
__device__ __forceinline__ void process_chunk(
    int c0, int lane,
    float T0, float T1, float T2, float T3, float T4, float T5, float p0,
    const float* __restrict__ pred, const float* __restrict__ tgt,
    const float* __restrict__ anc,
    float& a_nool, float& a_ncnt, float& a_box, float& a_objl,
    float& a_cls, float& a_ocnt)
{
    // ---- extract per-lane t0 (flat index lane*6) via shfl ----
    const int f   = lane * 6;
    const int src = f & 31;
    const float s0 = __shfl_sync(0xffffffffu, T0, src);
    const float s1 = __shfl_sync(0xffffffffu, T1, src);
    const float s2 = __shfl_sync(0xffffffffu, T2, src);
    const float s3 = __shfl_sync(0xffffffffu, T3, src);
    const float s4 = __shfl_sync(0xffffffffu, T4, src);
    const float s5 = __shfl_sync(0xffffffffu, T5, src);
    const int r = f >> 5;
    float t0 = s0;
    if (r == 1) t0 = s1; else if (r == 2) t0 = s2; else if (r == 3) t0 = s3;
    else if (r == 4) t0 = s4; else if (r == 5) t0 = s5;

    // ---- no-object BCE-with-logits on channel 0 (t == 0 cells) ----
    if (t0 == 0.0f) {
        a_nool += fmaxf(p0, 0.f) + log1pf(expf(-fabsf(p0)));
        a_ncnt += 1.f;
    }

    // ---- cooperative processing of obj cells (t == 1) ----
    unsigned bal = __ballot_sync(0xffffffffu, t0 == 1.0f);
    if (lane == 0) a_ocnt += (float)__popc(bal);

    while (bal) {
        const int i = __ffs(bal) - 1;
        bal &= bal - 1;
        const int cc = c0 + i;
        const int base = cc * CH;
        const float p0i = __shfl_sync(0xffffffffu, p0, i);

        // class logits: lane l holds k = l, l+32, l+64 (channels 5..84)
        float v0 = __ldg(&pred[base + 5  + lane]);
        float v1 = __ldg(&pred[base + 37 + lane]);
        float v2 = (lane < 16) ? __ldg(&pred[base + 69 + lane]) : 0.0f;
        const bool has2 = (lane < 16);

        // log-softmax pieces
        float mx = fmaxf(fmaxf(v0, v1), has2 ? v2 : -INFINITY);
        mx = warp_max(mx);
        float e  = expf(v0 - mx) + expf(v1 - mx) + (has2 ? expf(v2 - mx) : 0.f);
        float sx = v0 + v1 + (has2 ? v2 : 0.f);
        e  = warp_sum(e);
        sx = warp_sum(sx);
        const float lse = mx + logf(e);

        // box pred channels 1..4 (one sector, L1-resident after p0 fetch? no —
        // same 32B sector as p0 for aligned cells; cheap either way)
        float pb = (lane < 4) ? __ldg(&pred[base + 1 + lane]) : 0.f;
        const float p1 = __shfl_sync(0xffffffffu, pb, 0);
        const float p2 = __shfl_sync(0xffffffffu, pb, 1);
        const float p3 = __shfl_sync(0xffffffffu, pb, 2);
        const float p4 = __shfl_sync(0xffffffffu, pb, 3);
        // target channels 1..5 — sector already brought in by the coalesced
        // T-block load, so this is an L1 hit
        float tb = (lane < 5) ? __ldg(&tgt[cc * TCH + 1 + lane]) : 0.f;
        const float t1 = __shfl_sync(0xffffffffu, tb, 0);
        const float t2 = __shfl_sync(0xffffffffu, tb, 1);
        const float t3 = __shfl_sync(0xffffffffu, tb, 2);
        const float t4 = __shfl_sync(0xffffffffu, tb, 3);
        const float t5 = __shfl_sync(0xffffffffu, tb, 4);

        // gather class logit for target class k
        const int k = (int)t5;
        const int srcl = k & 31;
        const float g0 = __shfl_sync(0xffffffffu, v0, srcl);
        const float g1 = __shfl_sync(0xffffffffu, v1, srcl);
        const float g2 = __shfl_sync(0xffffffffu, v2, srcl);
        const float xk = (k < 32) ? g0 : ((k < 64) ? g1 : g2);

        const float logpy   = xk - lse;
        const float sumlogp = sx - (float)NCLS * lse;
        const float ce = -(0.9f * logpy + (0.1f / (float)NCLS) * sumlogp);

        // object loss: BCE-with-logits applied to sigmoid(p0) with t=1
        const float sg = 1.f / (1.f + expf(-p0i));
        const float ol = fmaxf(sg, 0.f) - sg + log1pf(expf(-fabsf(sg)));

        // decoded box + CIoU
        const int aidx = (cc / S2) % NA;
        const float aw = __ldg(&anc[aidx * 2 + 0]);
        const float ah = __ldg(&anc[aidx * 2 + 1]);
        const float bx = 1.f / (1.f + expf(-p1));
        const float by = 1.f / (1.f + expf(-p2));
        const float bw = expf(p3) * aw;
        const float bh = expf(p4) * ah;

        const float x1a = bx - bw * 0.5f, x1b = bx + bw * 0.5f;
        const float y1a = by - bh * 0.5f, y1b = by + bh * 0.5f;
        const float x2a = t1 - t3 * 0.5f, x2b = t1 + t3 * 0.5f;
        const float y2a = t2 - t4 * 0.5f, y2b = t2 + t4 * 0.5f;
        const float iw = fmaxf(fminf(x1b, x2b) - fmaxf(x1a, x2a), 0.f);
        const float ih = fmaxf(fminf(y1b, y2b) - fmaxf(y1a, y2a), 0.f);
        const float inter = iw * ih;
        const float uni = bw * bh + t3 * t4 - inter + EPSF;
        const float iou = inter / uni;
        const float cw  = fmaxf(x1b, x2b) - fminf(x1a, x2a);
        const float chh = fmaxf(y1b, y2b) - fminf(y1a, y2a);
        const float c2  = cw * cw + chh * chh + EPSF;
        const float rho2 = (t1 - bx) * (t1 - bx) + (t2 - by) * (t2 - by);
        const float fo = 4.0f / ((float)M_PI * (float)M_PI);
        const float dv = atanf(t3 / (t4 + EPSF)) - atanf(bw / (bh + EPSF));
        const float v  = fo * dv * dv;
        const float alpha = v / (1.f - iou + v + EPSF);
        const float ciou  = iou - rho2 / c2 - alpha * v;

        if (lane == 0) {
            a_box  += (1.f - ciou);
            a_objl += ol;
            a_cls  += ce;
        }
    }
}

__global__ __launch_bounds__(TPB)
void yolo_loss_fused(const float* __restrict__ pred,
                     const float* __restrict__ tgt,
                     const float* __restrict__ anc,
                     float* __restrict__ out,
                     int cells)
{
    const int lane = threadIdx.x & 31;
    const int wg   = (blockIdx.x * blockDim.x + threadIdx.x) >> 5;

    float a_nool = 0.f, a_ncnt = 0.f, a_box = 0.f, a_objl = 0.f,
          a_cls = 0.f, a_ocnt = 0.f;

    const int step = NWARPS * 32;
    // grid-stride over 32-cell chunks, software-pipelined in pairs so up to
    // 14 LDGs are in flight before any dependent work begins
    for (int c0 = wg * 32; c0 < cells; c0 += 2 * step) {
        const int cB = c0 + step;
        const int ta = c0 * 6;
        const float A0 = __ldg(&tgt[ta + lane]);
        const float A1 = __ldg(&tgt[ta + lane + 32]);
        const float A2 = __ldg(&tgt[ta + lane + 64]);
        const float A3 = __ldg(&tgt[ta + lane + 96]);
        const float A4 = __ldg(&tgt[ta + lane + 128]);
        const float A5 = __ldg(&tgt[ta + lane + 160]);
        const float pA = __ldg(&pred[(c0 + lane) * CH]);

        const bool hb = (cB < cells);
        float B0 = 0.f, B1 = 0.f, B2 = 0.f, B3 = 0.f, B4 = 0.f, B5 = 0.f,
              pB = 0.f;
        if (hb) {
            const int tb = cB * 6;
            B0 = __ldg(&tgt[tb + lane]);
            B1 = __ldg(&tgt[tb + lane + 32]);
            B2 = __ldg(&tgt[tb + lane + 64]);
            B3 = __ldg(&tgt[tb + lane + 96]);
            B4 = __ldg(&tgt[tb + lane + 128]);
            B5 = __ldg(&tgt[tb + lane + 160]);
            pB = __ldg(&pred[(cB + lane) * CH]);
        }

        process_chunk(c0, lane, A0, A1, A2, A3, A4, A5, pA,
                      pred, tgt, anc, a_nool, a_ncnt, a_box, a_objl, a_cls, a_ocnt);
        if (hb)
            process_chunk(cB, lane, B0, B1, B2, B3, B4, B5, pB,
                          pred, tgt, anc, a_nool, a_ncnt, a_box, a_objl, a_cls, a_ocnt);
    }

    // ---- block reduction to per-block double partial ----
    a_nool = warp_sum(a_nool);
    a_ncnt = warp_sum(a_ncnt);
    a_box  = warp_sum(a_box);
    a_objl = warp_sum(a_objl);
    a_cls  = warp_sum(a_cls);
    a_ocnt = warp_sum(a_ocnt);

    __shared__ float sh[8][6];
    const int wid = threadIdx.x >> 5;
    if (lane == 0) {
        sh[wid][0] = a_nool; sh[wid][1] = a_ncnt; sh[wid][2] = a_box;
        sh[wid][3] = a_objl; sh[wid][4] = a_cls;  sh[wid][5] = a_ocnt;
    }
    __syncthreads();

    __shared__ bool amlast;
    if (threadIdx.x == 0) {
        const int nw = blockDim.x >> 5;
        #pragma unroll
        for (int q = 0; q < 6; q++) {
            double d = 0.0;
            for (int w = 0; w < nw; w++) d += (double)sh[w][q];
            g_part[blockIdx.x * 6 + q] = d;
        }
        __threadfence();
        const unsigned old = atomicAdd(&g_done, 1u);
        amlast = (old == (unsigned)(gridDim.x - 1));
    }
    __syncthreads();

    // ---- last block performs the deterministic final reduction ----
    if (amlast) {
        __threadfence();  // acquire: see all g_part writes
        double acc[6] = {0, 0, 0, 0, 0, 0};
        volatile double* gp = g_part;
        for (int i = threadIdx.x; i < BLOCKS; i += TPB) {
            #pragma unroll
            for (int q = 0; q < 6; q++) acc[q] += gp[i * 6 + q];
        }
        #pragma unroll
        for (int q = 0; q < 6; q++) acc[q] = warp_sum_d(acc[q]);

        __shared__ double fsh[8][6];
        if (lane == 0) {
            #pragma unroll
            for (int q = 0; q < 6; q++) fsh[wid][q] = acc[q];
        }
        __syncthreads();
        if (threadIdx.x == 0) {
            double tot[6] = {0, 0, 0, 0, 0, 0};
            #pragma unroll
            for (int w = 0; w < 8; w++)
                #pragma unroll
                for (int q = 0; q < 6; q++) tot[q] += fsh[w][q];
            const double nool = tot[0] / fmax(tot[1], 1.0);
            const double od   = fmax(tot[5], 1.0);
            out[0] = (float)(2.0 * (tot[2] / od) + tot[3] / od + nool + tot[4] / od);
            __threadfence();
            g_done = 0;  // reset for next graph replay
        }
    }
}

extern "C" void kernel_launch(void* const* d_in, const int* in_sizes, int n_in,
                              void* d_out, int out_size)
{
    (void)n_in; (void)out_size;
    const float* pred = (const float*)d_in[0];
    const float* tgt  = (const float*)d_in[1];
    const float* anc  = (const float*)d_in[2];
    float* out = (float*)d_out;

    const int cells = in_sizes[0] / CH;   // 614400
    yolo_loss_fused<<<BLOCKS, TPB>>>(pred, tgt, anc, out, cells);
}